// round 2
// baseline (speedup 1.0000x reference)
#include <cuda_runtime.h>
#include <cuda_bf16.h>

// CASSI forward A^T(A(x)):
//   y2[b,m,j]    = sum_{l : 0<=j-2l<N} x[b,l,m,j-2l]*phi[l,m,j-2l]
//   out[b,l,m,n] = phi[l,m,n] * y2[b,m,n+2l]
// One CTA per (b,m) row. L=28, N=256, STRIDE=2, n_out=310.

#define LBANDS 28
#define NCOLS  256
#define STRIDE2 2
#define NOUT   (NCOLS + STRIDE2 * (LBANDS - 1))   // 310
#define THREADS 256

// smem layout (floats): prod[28][256] | phis[28][256] | y2[320]
#define SM_PROD 0
#define SM_PHI  (LBANDS * NCOLS)
#define SM_Y2   (2 * LBANDS * NCOLS)
#define SM_FLOATS (2 * LBANDS * NCOLS + 320)

__global__ __launch_bounds__(THREADS, 3)
void cassi_kernel(const float* __restrict__ x,
                  const float* __restrict__ phi,
                  float* __restrict__ out,
                  int M, int L_times_MN /* L*M*N */)
{
    extern __shared__ float sm[];
    float* prod = sm + SM_PROD;
    float* phis = sm + SM_PHI;
    float* y2   = sm + SM_Y2;

    const int m = blockIdx.x;         // row
    const int b = blockIdx.y;         // batch
    const int tid = threadIdx.x;

    const int lsub = tid >> 6;        // 0..3 : band sub-index
    const int c4   = (tid & 63) << 2; // float4 column start, 0..252

    const long band_step   = (long)M * NCOLS;               // stride between bands
    const long xrow_base   = (long)b * L_times_MN + (long)m * NCOLS;
    const long phirow_base = (long)m * NCOLS;               // <-- R1 fix: phi row offset

    // ---- phase 1: stage prod = x*phi and phi into smem (float4, coalesced) ----
#pragma unroll
    for (int lb = 0; lb < LBANDS / 4; ++lb) {
        const int l = lb * 4 + lsub;
        const float4 xv = *reinterpret_cast<const float4*>(
            x + xrow_base + (long)l * band_step + c4);
        const float4 pv = *reinterpret_cast<const float4*>(
            phi + phirow_base + (long)l * band_step + c4);
        float4 pr;
        pr.x = xv.x * pv.x; pr.y = xv.y * pv.y;
        pr.z = xv.z * pv.z; pr.w = xv.w * pv.w;
        *reinterpret_cast<float4*>(&prod[l * NCOLS + c4]) = pr;
        *reinterpret_cast<float4*>(&phis[l * NCOLS + c4]) = pv;
    }
    __syncthreads();

    // ---- phase 2: gather-style scatter-add result y2[j] (no atomics) ----
    // y2[j] = sum over l with 0 <= j-2l < N of prod[l][j-2l]
    for (int j = tid; j < NOUT; j += THREADS) {
        const int lmin = (j >= NCOLS) ? ((j - (NCOLS - 2)) >> 1) : 0;
        const int jh   = j >> 1;
        const int lmax = jh < (LBANDS - 1) ? jh : (LBANDS - 1);
        float s = 0.0f;
        for (int l = lmin; l <= lmax; ++l)
            s += prod[l * NCOLS + (j - 2 * l)];
        y2[j] = s;
    }
    __syncthreads();

    // ---- phase 3: out[b,l,m,n] = phi[l,m,n] * y2[n+2l] (float4 stores) ----
#pragma unroll
    for (int lb = 0; lb < LBANDS / 4; ++lb) {
        const int l = lb * 4 + lsub;
        const float4 pv = *reinterpret_cast<const float4*>(&phis[l * NCOLS + c4]);
        const int jb = c4 + 2 * l;
        float4 ov;
        ov.x = pv.x * y2[jb + 0];
        ov.y = pv.y * y2[jb + 1];
        ov.z = pv.z * y2[jb + 2];
        ov.w = pv.w * y2[jb + 3];
        *reinterpret_cast<float4*>(
            out + xrow_base + (long)l * band_step + c4) = ov;
    }
}

extern "C" void kernel_launch(void* const* d_in, const int* in_sizes, int n_in,
                              void* d_out, int out_size)
{
    const float* x   = (const float*)d_in[0];   // [B, L, M, N]
    const float* phi = (const float*)d_in[1];   // [L, M, N]
    float* out = (float*)d_out;

    const int LMN = in_sizes[1];                // L*M*N
    const int M   = NCOLS;                      // M == 256 (square aperture)
    const int B   = in_sizes[0] / LMN;          // batch

    static bool attr_set = false;
    if (!attr_set) {
        cudaFuncSetAttribute(cassi_kernel,
                             cudaFuncAttributeMaxDynamicSharedMemorySize,
                             SM_FLOATS * (int)sizeof(float));
        attr_set = true;
    }

    dim3 grid(M, B);
    cassi_kernel<<<grid, THREADS, SM_FLOATS * sizeof(float)>>>(
        x, phi, out, M, LMN);
}

// round 3
// speedup vs baseline: 1.2668x; 1.2668x over previous
#include <cuda_runtime.h>
#include <cuda_bf16.h>

// CASSI forward A^T(A(x)):
//   y2[b,m,j]    = sum_{l : 0<=j-2l<N} x[b,l,m,j-2l]*phi[l,m,j-2l]
//   out[b,l,m,n] = phi[l,m,n] * y2[b,m,n+2l]
// One CTA per (b,m) row. L=28, N=256, STRIDE=2, n_out=310.
//
// R3: smem = prod + dual-copy y2 only (30.5KB) -> 5 CTAs/SM; phi re-read from
// global (L2-resident) in phase 3; phase-3 y2 reads are aligned LDS.128 via the
// 2-shifted duplicate y2s (band parity is warp-uniform).

#define LBANDS 28
#define NCOLS  256
#define NC4    (NCOLS / 4)                        // 64 float4 per row
#define NOUT   (NCOLS + 2 * (LBANDS - 1))         // 310
#define THREADS 256

// smem floats: prod[28*256] | y2[320] | y2s[320]  (y2s[j] == y2[j+2])
#define SM_PROD   0
#define SM_Y2     (LBANDS * NCOLS)
#define SM_Y2S    (LBANDS * NCOLS + 320)
#define SM_FLOATS (LBANDS * NCOLS + 640)

__global__ __launch_bounds__(THREADS, 5)
void cassi_kernel(const float4* __restrict__ x4,
                  const float4* __restrict__ phi4,
                  float4* __restrict__ out4,
                  int M, int LMN4 /* L*M*N/4 */)
{
    extern __shared__ float sm[];
    float*  prod  = sm + SM_PROD;
    float4* prod4 = reinterpret_cast<float4*>(prod);
    float*  y2    = sm + SM_Y2;
    float*  y2s   = sm + SM_Y2S;

    const int m   = blockIdx.x;
    const int b   = blockIdx.y;
    const int tid = threadIdx.x;

    const int lsub = tid >> 6;        // 0..3, uniform per warp-pair
    const int c    = tid & 63;        // float4 column 0..63

    const int band4    = M * NC4;                 // float4 stride between bands
    const int xrow4    = b * LMN4 + m * NC4;      // x/out row base (float4 units)
    const int phirow4  = m * NC4;                 // phi row base

    // ---- phase 1: prod = x*phi -> smem (LDG.128 x2, STS.128 x1 per band) ----
    {
        int xo = xrow4  + lsub * band4 + c;
        int po = phirow4 + lsub * band4 + c;
        int so = lsub * NC4 + c;
#pragma unroll
        for (int k = 0; k < LBANDS / 4; ++k) {
            const float4 xv = x4[xo];
            const float4 pv = phi4[po];
            float4 pr;
            pr.x = xv.x * pv.x; pr.y = xv.y * pv.y;
            pr.z = xv.z * pv.z; pr.w = xv.w * pv.w;
            prod4[so] = pr;
            xo += 4 * band4; po += 4 * band4; so += 4 * NC4;
        }
    }
    __syncthreads();

    // ---- phase 2: y2[j] = sum_l prod[l][j-2l], plus shifted copy y2s ----
#pragma unroll
    for (int t = 0; t < 2; ++t) {
        const int j = tid + t * THREADS;
        if (j < NOUT) {
            const int lmin = (j >= NCOLS) ? ((j - (NCOLS - 2)) >> 1) : 0;
            const int jh   = j >> 1;
            const int lmax = jh < (LBANDS - 1) ? jh : (LBANDS - 1);
            float s = 0.0f;
            for (int l = lmin; l <= lmax; ++l)
                s += prod[l * NCOLS + (j - 2 * l)];
            y2[j] = s;
            if (j >= 2) y2s[j - 2] = s;   // y2s[j'] = y2[j'+2]
        }
    }
    __syncthreads();

    // ---- phase 3: out = phi * y2[n+2l]; phi re-read (L2), y2 via LDS.128 ----
    {
        // band l = 4k + lsub; parity of l == parity of lsub (warp-uniform)
        const float* ybase = (lsub & 1) ? y2s : y2;
        // float index of the aligned float4 covering y2[c4 + 2l ...]:
        // even lsub: c4 + 2*lsub;  odd lsub: c4 + 2*lsub - 2. Both %4 == 0.
        int yo4 = ((c << 2) + 2 * lsub - ((lsub & 1) << 1)) >> 2; // float4 idx
        int oo = xrow4  + lsub * band4 + c;
        int po = phirow4 + lsub * band4 + c;
#pragma unroll
        for (int k = 0; k < LBANDS / 4; ++k) {
            const float4 pv = phi4[po];
            const float4 yv = reinterpret_cast<const float4*>(ybase)[yo4];
            float4 ov;
            ov.x = pv.x * yv.x; ov.y = pv.y * yv.y;
            ov.z = pv.z * yv.z; ov.w = pv.w * yv.w;
            out4[oo] = ov;
            oo += 4 * band4; po += 4 * band4;
            yo4 += 2;                      // +8 floats = 4 bands * stride 2
        }
    }
}

extern "C" void kernel_launch(void* const* d_in, const int* in_sizes, int n_in,
                              void* d_out, int out_size)
{
    const float4* x4   = (const float4*)d_in[0];   // [B, L, M, N]
    const float4* phi4 = (const float4*)d_in[1];   // [L, M, N]
    float4* out4 = (float4*)d_out;

    const int LMN  = in_sizes[1];        // L*M*N
    const int M    = NCOLS;              // M == 256
    const int B    = in_sizes[0] / LMN;  // batch
    const int LMN4 = LMN / 4;

    static bool attr_set = false;
    if (!attr_set) {
        cudaFuncSetAttribute(cassi_kernel,
                             cudaFuncAttributeMaxDynamicSharedMemorySize,
                             SM_FLOATS * (int)sizeof(float));
        attr_set = true;
    }

    dim3 grid(M, B);
    cassi_kernel<<<grid, THREADS, SM_FLOATS * sizeof(float)>>>(
        x4, phi4, out4, M, LMN4);
}